// round 1
// baseline (speedup 1.0000x reference)
#include <cuda_runtime.h>
#include <math.h>

#define TT   4096
#define CC   1024
#define HH   16
#define DD   64
#define WIN  1024
#define SCALE_F 0.12f

// scratch (allocation-free contract: __device__ globals)
__device__ float g_qkv[TT * 3 * CC];   // 48 MB
__device__ float g_q[HH * TT * DD];    // 16 MB
__device__ float g_k[HH * TT * DD];
__device__ float g_v[HH * TT * DD];
__device__ float g_att[TT * CC];       // 16 MB

// ---------------------------------------------------------------------------
// C[M,N] = A[M,K] * B[N,K]^T   (both operands K-contiguous, row-major)
// 128x128 tile, BK=8, 256 threads, 8x8 micro-tile per thread.
// ---------------------------------------------------------------------------
__global__ __launch_bounds__(256, 2)
void sgemm_nt(const float* __restrict__ A, const float* __restrict__ B,
              float* __restrict__ C, int M, int N, int K)
{
    __shared__ float As[8][128];
    __shared__ float Bs[8][128];
    const int tid = threadIdx.x;
    const int tx = tid & 15, ty = tid >> 4;
    const int bm = blockIdx.y * 128, bn = blockIdx.x * 128;
    const int lr = tid >> 1;          // 0..127
    const int lk = (tid & 1) * 4;     // 0 or 4

    const float* Ag = A + (size_t)(bm + lr) * K + lk;
    const float* Bg = B + (size_t)(bn + lr) * K + lk;

    float acc[8][8];
    #pragma unroll
    for (int i = 0; i < 8; i++)
        #pragma unroll
        for (int j = 0; j < 8; j++) acc[i][j] = 0.f;

    float4 av = *(const float4*)Ag;
    float4 bv = *(const float4*)Bg;

    for (int k0 = 0; k0 < K; k0 += 8) {
        __syncthreads();
        As[lk + 0][lr] = av.x; As[lk + 1][lr] = av.y;
        As[lk + 2][lr] = av.z; As[lk + 3][lr] = av.w;
        Bs[lk + 0][lr] = bv.x; Bs[lk + 1][lr] = bv.y;
        Bs[lk + 2][lr] = bv.z; Bs[lk + 3][lr] = bv.w;
        __syncthreads();
        if (k0 + 8 < K) {
            Ag += 8; Bg += 8;
            av = *(const float4*)Ag;
            bv = *(const float4*)Bg;
        }
        #pragma unroll
        for (int kk = 0; kk < 8; kk++) {
            float4 a0 = *(const float4*)&As[kk][ty * 8];
            float4 a1 = *(const float4*)&As[kk][ty * 8 + 4];
            float4 b0 = *(const float4*)&Bs[kk][tx * 8];
            float4 b1 = *(const float4*)&Bs[kk][tx * 8 + 4];
            float a[8] = {a0.x, a0.y, a0.z, a0.w, a1.x, a1.y, a1.z, a1.w};
            float b[8] = {b0.x, b0.y, b0.z, b0.w, b1.x, b1.y, b1.z, b1.w};
            #pragma unroll
            for (int i = 0; i < 8; i++)
                #pragma unroll
                for (int j = 0; j < 8; j++)
                    acc[i][j] += a[i] * b[j];
        }
    }
    #pragma unroll
    for (int i = 0; i < 8; i++) {
        float* Cr = C + (size_t)(bm + ty * 8 + i) * N + bn + tx * 8;
        *(float4*)(Cr)     = make_float4(acc[i][0], acc[i][1], acc[i][2], acc[i][3]);
        *(float4*)(Cr + 4) = make_float4(acc[i][4], acc[i][5], acc[i][6], acc[i][7]);
    }
}

// ---------------------------------------------------------------------------
// Split qkv row into per-head Q/K/V with RMSNorm + RoPE (Q,K) and 0.5*V.
// grid = T blocks, 512 threads (warp w = head w, lane owns dims 2*lane, 2*lane+1)
// ---------------------------------------------------------------------------
__global__ void qkv_post(const float* __restrict__ cosT, const float* __restrict__ sinT,
                         const float* __restrict__ qw, const float* __restrict__ kw)
{
    const int t    = blockIdx.x;
    const int h    = threadIdx.x >> 5;
    const int lane = threadIdx.x & 31;
    const int d0   = lane * 2;
    const float* row = g_qkv + (size_t)t * (3 * CC);

    float cv = 0.f, sv = 0.f;
    if (lane < 16) { cv = cosT[t * 16 + lane]; sv = sinT[t * 16 + lane]; }

    // ---- Q ----
    float2 q2 = *(const float2*)(row + h * 64 + d0);
    float ss = q2.x * q2.x + q2.y * q2.y;
    #pragma unroll
    for (int off = 16; off; off >>= 1) ss += __shfl_xor_sync(0xffffffffu, ss, off);
    float rn = rsqrtf(ss * (1.f / 64.f) + 1e-6f);
    float qa = q2.x * rn * qw[d0];
    float qb = q2.y * rn * qw[d0 + 1];
    if (lane < 16) {
        float e = qa, od = qb;
        qa = e * cv - od * sv;
        qb = e * sv + od * cv;
    }
    *(float2*)(g_q + ((size_t)h * TT + t) * 64 + d0) = make_float2(qa, qb);

    // ---- K ----
    float2 k2 = *(const float2*)(row + CC + h * 64 + d0);
    float ssk = k2.x * k2.x + k2.y * k2.y;
    #pragma unroll
    for (int off = 16; off; off >>= 1) ssk += __shfl_xor_sync(0xffffffffu, ssk, off);
    float rk = rsqrtf(ssk * (1.f / 64.f) + 1e-6f);
    float ka = k2.x * rk * kw[d0];
    float kb = k2.y * rk * kw[d0 + 1];
    if (lane < 16) {
        float e = ka, od = kb;
        ka = e * cv - od * sv;
        kb = e * sv + od * cv;
    }
    *(float2*)(g_k + ((size_t)h * TT + t) * 64 + d0) = make_float2(ka, kb);

    // ---- V ----
    float2 v2 = *(const float2*)(row + 2 * CC + h * 64 + d0);
    *(float2*)(g_v + ((size_t)h * TT + t) * 64 + d0) =
        make_float2(v2.x * 0.5f, v2.y * 0.5f);
}

// ---------------------------------------------------------------------------
// Sliding-window flash attention, fp32. 64x64 tiles, online softmax.
// grid = (T/64, H), 256 threads; thread (tx,ty) owns 4x4 of the 64x64 tile.
// Row stats replicated across the 16-lane tx group via shfl_xor (<=8).
// ---------------------------------------------------------------------------
__global__ void attn_win()
{
    extern __shared__ float sm[];
    float* Qs = sm;                 // [64][68] transposed: Qs[d][r]
    float* Ks = Qs + 64 * 68;       // [64][68] transposed: Ks[d][n]
    float* Vs = Ks + 64 * 68;       // [64][64] natural:    Vs[n][c]
    float* Ps = Vs + 64 * 64;       // [64][68] transposed: Ps[n][r]

    const int h  = blockIdx.y;
    const int qb = blockIdx.x;
    const int t0 = qb * 64;
    const float* Qg = g_q + ((size_t)h * TT + t0) * 64;
    const float* Kg = g_k + (size_t)h * TT * 64;
    const float* Vg = g_v + (size_t)h * TT * 64;

    const int tid = threadIdx.x;
    const int tx = tid & 15, ty = tid >> 4;

    // load Q transposed
    #pragma unroll
    for (int it = 0; it < 4; it++) {
        int idx = tid + it * 256;
        int r = idx >> 4, g = (idx & 15) * 4;
        float4 v = *(const float4*)(Qg + r * 64 + g);
        Qs[(g + 0) * 68 + r] = v.x; Qs[(g + 1) * 68 + r] = v.y;
        Qs[(g + 2) * 68 + r] = v.z; Qs[(g + 3) * 68 + r] = v.w;
    }

    float o[4][4];
    float mi[4], li[4];
    #pragma unroll
    for (int i = 0; i < 4; i++) {
        mi[i] = -1e30f; li[i] = 0.f;
        #pragma unroll
        for (int j = 0; j < 4; j++) o[i][j] = 0.f;
    }

    const int jb0 = (qb >= 16) ? (qb - 16) : 0;
    for (int jb = jb0; jb <= qb; jb++) {
        const int s0 = jb * 64;
        __syncthreads();  // prev PV done (and first-iter Q load visible)
        #pragma unroll
        for (int it = 0; it < 4; it++) {
            int idx = tid + it * 256;
            int r = idx >> 4, g = (idx & 15) * 4;
            float4 kv = *(const float4*)(Kg + (size_t)(s0 + r) * 64 + g);
            Ks[(g + 0) * 68 + r] = kv.x; Ks[(g + 1) * 68 + r] = kv.y;
            Ks[(g + 2) * 68 + r] = kv.z; Ks[(g + 3) * 68 + r] = kv.w;
            float4 vv = *(const float4*)(Vg + (size_t)(s0 + r) * 64 + g);
            *(float4*)&Vs[r * 64 + g] = vv;
        }
        __syncthreads();

        // S = Q K^T
        float s[4][4];
        #pragma unroll
        for (int i = 0; i < 4; i++)
            #pragma unroll
            for (int j = 0; j < 4; j++) s[i][j] = 0.f;
        #pragma unroll
        for (int dd = 0; dd < 64; dd++) {
            float4 a = *(const float4*)&Qs[dd * 68 + ty * 4];
            float4 b = *(const float4*)&Ks[dd * 68 + tx * 4];
            float aa[4] = {a.x, a.y, a.z, a.w};
            float bb[4] = {b.x, b.y, b.z, b.w};
            #pragma unroll
            for (int i = 0; i < 4; i++)
                #pragma unroll
                for (int j = 0; j < 4; j++) s[i][j] += aa[i] * bb[j];
        }

        // mask + scale
        #pragma unroll
        for (int i = 0; i < 4; i++) {
            int rg = t0 + ty * 4 + i;
            #pragma unroll
            for (int j = 0; j < 4; j++) {
                int cg = s0 + tx * 4 + j;
                int diff = rg - cg;
                s[i][j] = (diff >= 0 && diff < WIN) ? s[i][j] * SCALE_F : -1e30f;
            }
        }

        // online softmax (row stats across tx group)
        #pragma unroll
        for (int i = 0; i < 4; i++) {
            float tm = fmaxf(fmaxf(s[i][0], s[i][1]), fmaxf(s[i][2], s[i][3]));
            #pragma unroll
            for (int off = 8; off; off >>= 1)
                tm = fmaxf(tm, __shfl_xor_sync(0xffffffffu, tm, off));
            float mn = fmaxf(mi[i], tm);
            float alpha = __expf(mi[i] - mn);
            float rs = 0.f;
            #pragma unroll
            for (int j = 0; j < 4; j++) {
                s[i][j] = __expf(s[i][j] - mn);
                rs += s[i][j];
            }
            #pragma unroll
            for (int off = 8; off; off >>= 1)
                rs += __shfl_xor_sync(0xffffffffu, rs, off);
            li[i] = li[i] * alpha + rs;
            mi[i] = mn;
            #pragma unroll
            for (int j = 0; j < 4; j++) o[i][j] *= alpha;
        }

        // store P transposed: Ps[n][r]
        #pragma unroll
        for (int j = 0; j < 4; j++)
            #pragma unroll
            for (int i = 0; i < 4; i++)
                Ps[(tx * 4 + j) * 68 + ty * 4 + i] = s[i][j];
        __syncthreads();

        // O += P V
        #pragma unroll
        for (int n = 0; n < 64; n++) {
            float4 a = *(const float4*)&Ps[n * 68 + ty * 4];
            float4 b = *(const float4*)&Vs[n * 64 + tx * 4];
            float aa[4] = {a.x, a.y, a.z, a.w};
            float bb[4] = {b.x, b.y, b.z, b.w};
            #pragma unroll
            for (int i = 0; i < 4; i++)
                #pragma unroll
                for (int j = 0; j < 4; j++) o[i][j] += aa[i] * bb[j];
        }
    }

    #pragma unroll
    for (int i = 0; i < 4; i++) {
        float inv = 1.f / li[i];
        float* out = g_att + (size_t)(t0 + ty * 4 + i) * CC + h * 64 + tx * 4;
        *(float4*)out = make_float4(o[i][0] * inv, o[i][1] * inv,
                                    o[i][2] * inv, o[i][3] * inv);
    }
}

// ---------------------------------------------------------------------------
extern "C" void kernel_launch(void* const* d_in, const int* in_sizes, int n_in,
                              void* d_out, int out_size)
{
    const float* x    = (const float*)d_in[0];
    // d_in[1]=tokens (unused), d_in[2]=pos (identity, unused)
    const float* wqkv = (const float*)d_in[3];
    const float* wo   = (const float*)d_in[4];
    const float* qnw  = (const float*)d_in[5];
    const float* knw  = (const float*)d_in[6];
    const float* cosT = (const float*)d_in[7];
    const float* sinT = (const float*)d_in[8];
    float* out = (float*)d_out;

    float *p_qkv = nullptr, *p_att = nullptr;
    cudaGetSymbolAddress((void**)&p_qkv, g_qkv);
    cudaGetSymbolAddress((void**)&p_att, g_att);

    // 1) qkv = x @ w_qkv^T   (4096 x 3072)
    sgemm_nt<<<dim3(3072 / 128, 4096 / 128), 256>>>(x, wqkv, p_qkv, TT, 3 * CC, CC);

    // 2) rmsnorm + rope + v*0.5, scatter to [H][T][64]
    qkv_post<<<TT, 512>>>(cosT, sinT, qnw, knw);

    // 3) sliding-window attention -> g_att (4096 x 1024, head-concat layout)
    size_t smem = (size_t)(64 * 68 * 3 + 64 * 64) * sizeof(float);  // 68608 B
    cudaFuncSetAttribute(attn_win, cudaFuncAttributeMaxDynamicSharedMemorySize, (int)smem);
    attn_win<<<dim3(TT / 64, HH), 256, smem>>>();

    // 4) out = att @ w_o^T   (4096 x 1024)
    sgemm_nt<<<dim3(1024 / 128, 4096 / 128), 256>>>(p_att, wo, out, TT, CC, CC);
}

// round 8
// speedup vs baseline: 1.7629x; 1.7629x over previous
#include <cuda_runtime.h>
#include <cuda_bf16.h>
#include <cstdint>
#include <math.h>

#define TT   4096
#define CC   1024
#define HH   16
#define DD   64
#define WIN  1024
#define SCALE_F 0.12f

// scratch (allocation-free contract: __device__ globals)
__device__ float g_qkv[TT * 3 * CC];   // 48 MB
__device__ float g_q[HH * TT * DD];    // 16 MB
__device__ float g_k[HH * TT * DD];
__device__ float g_v[HH * TT * DD];
__device__ float g_att[TT * CC];       // 16 MB

__device__ __forceinline__ uint32_t f2tf(float f) {
    uint32_t u;
    asm("cvt.rn.tf32.f32 %0, %1;" : "=r"(u) : "f"(f));
    return u;
}

__device__ __forceinline__ void mma_tf32_16n8k8(float* c, const uint32_t* a,
                                                const uint32_t* b) {
    asm volatile(
        "mma.sync.aligned.m16n8k8.row.col.f32.tf32.tf32.f32 "
        "{%0,%1,%2,%3}, {%4,%5,%6,%7}, {%8,%9}, {%0,%1,%2,%3};"
        : "+f"(c[0]), "+f"(c[1]), "+f"(c[2]), "+f"(c[3])
        : "r"(a[0]), "r"(a[1]), "r"(a[2]), "r"(a[3]), "r"(b[0]), "r"(b[1]));
}

// ===========================================================================
// C[M,N] = A[M,K] * B[N,K]^T  via mma.sync tf32 (tensor pipe, base sm_103).
// 128x128 CTA tile, 256 threads = 8 warps (4x2 m-n), warp tile 32x64.
// K-chunk 32, inputs fp32 -> cvt.rn.tf32 on the smem store.
// ===========================================================================
#define SSTR 36   // smem row stride in floats (float4-aligned pad, conflict-free)

__global__ __launch_bounds__(256, 2)
void gemm_mma(const float* __restrict__ A, const float* __restrict__ B,
              float* __restrict__ C, int M, int N, int K)
{
    __shared__ uint32_t As[128 * SSTR];
    __shared__ uint32_t Bs[128 * SSTR];

    const int tid = threadIdx.x;
    const int wid = tid >> 5, lid = tid & 31;
    const int g = lid >> 2, t = lid & 3;         // mma group / thread-in-group
    const int wm = wid >> 1, wn = wid & 1;        // warp tile coords (4x2)
    const int bm = blockIdx.y * 128, bn = blockIdx.x * 128;

    // global staging coords: 1024 float4 slots per tile, 4 per thread
    const int grow = tid >> 3;          // we reuse per-iter: idx>>3
    (void)grow;

    float acc[2][8][4];
    #pragma unroll
    for (int i = 0; i < 2; i++)
        #pragma unroll
        for (int j = 0; j < 8; j++)
            #pragma unroll
            for (int l = 0; l < 4; l++) acc[i][j][l] = 0.f;

    for (int c0 = 0; c0 < K; c0 += 32) {
        __syncthreads();
        const float* Ag = A + (size_t)bm * K + c0;
        const float* Bg = B + (size_t)bn * K + c0;
        #pragma unroll
        for (int i = 0; i < 4; i++) {
            int idx = tid + i * 256;
            int row = idx >> 3, c4 = (idx & 7) * 4;   // 128 rows x 8 float4-groups
            float4 a = *(const float4*)(Ag + (size_t)row * K + c4);
            float4 b = *(const float4*)(Bg + (size_t)row * K + c4);
            uint32_t* pa = &As[row * SSTR + c4];
            uint32_t* pb = &Bs[row * SSTR + c4];
            *(uint4*)pa = make_uint4(f2tf(a.x), f2tf(a.y), f2tf(a.z), f2tf(a.w));
            *(uint4*)pb = make_uint4(f2tf(b.x), f2tf(b.y), f2tf(b.z), f2tf(b.w));
        }
        __syncthreads();

        #pragma unroll
        for (int ks = 0; ks < 4; ks++) {
            const int kb = ks * 8;
            uint32_t af[2][4];
            #pragma unroll
            for (int mt = 0; mt < 2; mt++) {
                int r0 = wm * 32 + mt * 16 + g;
                af[mt][0] = As[(r0    ) * SSTR + kb + t];
                af[mt][1] = As[(r0 + 8) * SSTR + kb + t];
                af[mt][2] = As[(r0    ) * SSTR + kb + t + 4];
                af[mt][3] = As[(r0 + 8) * SSTR + kb + t + 4];
            }
            uint32_t bf[8][2];
            #pragma unroll
            for (int nt = 0; nt < 8; nt++) {
                int n0 = wn * 64 + nt * 8 + g;
                bf[nt][0] = Bs[n0 * SSTR + kb + t];
                bf[nt][1] = Bs[n0 * SSTR + kb + t + 4];
            }
            #pragma unroll
            for (int mt = 0; mt < 2; mt++)
                #pragma unroll
                for (int nt = 0; nt < 8; nt++)
                    mma_tf32_16n8k8(acc[mt][nt], af[mt], bf[nt]);
        }
    }

    // epilogue: c0,c1 -> (row0, col..col+1); c2,c3 -> (row0+8, ...)
    #pragma unroll
    for (int mt = 0; mt < 2; mt++) {
        int row0 = bm + wm * 32 + mt * 16 + g;
        #pragma unroll
        for (int nt = 0; nt < 8; nt++) {
            int col = bn + wn * 64 + nt * 8 + 2 * t;
            *(float2*)(C + (size_t)row0 * N + col) =
                make_float2(acc[mt][nt][0], acc[mt][nt][1]);
            *(float2*)(C + (size_t)(row0 + 8) * N + col) =
                make_float2(acc[mt][nt][2], acc[mt][nt][3]);
        }
    }
}

// ---------------------------------------------------------------------------
// Split qkv row into per-head Q/K/V with RMSNorm + RoPE (Q,K) and 0.5*V.
// ---------------------------------------------------------------------------
__global__ void qkv_post(const float* __restrict__ cosT, const float* __restrict__ sinT,
                         const float* __restrict__ qw, const float* __restrict__ kw)
{
    const int t    = blockIdx.x;
    const int h    = threadIdx.x >> 5;
    const int lane = threadIdx.x & 31;
    const int d0   = lane * 2;
    const float* row = g_qkv + (size_t)t * (3 * CC);

    float cv = 0.f, sv = 0.f;
    if (lane < 16) { cv = cosT[t * 16 + lane]; sv = sinT[t * 16 + lane]; }

    // ---- Q ----
    float2 q2 = *(const float2*)(row + h * 64 + d0);
    float ss = q2.x * q2.x + q2.y * q2.y;
    #pragma unroll
    for (int off = 16; off; off >>= 1) ss += __shfl_xor_sync(0xffffffffu, ss, off);
    float rn = rsqrtf(ss * (1.f / 64.f) + 1e-6f);
    float qa = q2.x * rn * qw[d0];
    float qb = q2.y * rn * qw[d0 + 1];
    if (lane < 16) {
        float e = qa, od = qb;
        qa = e * cv - od * sv;
        qb = e * sv + od * cv;
    }
    *(float2*)(g_q + ((size_t)h * TT + t) * 64 + d0) = make_float2(qa, qb);

    // ---- K ----
    float2 k2 = *(const float2*)(row + CC + h * 64 + d0);
    float ssk = k2.x * k2.x + k2.y * k2.y;
    #pragma unroll
    for (int off = 16; off; off >>= 1) ssk += __shfl_xor_sync(0xffffffffu, ssk, off);
    float rk = rsqrtf(ssk * (1.f / 64.f) + 1e-6f);
    float ka = k2.x * rk * kw[d0];
    float kb = k2.y * rk * kw[d0 + 1];
    if (lane < 16) {
        float e = ka, od = kb;
        ka = e * cv - od * sv;
        kb = e * sv + od * cv;
    }
    *(float2*)(g_k + ((size_t)h * TT + t) * 64 + d0) = make_float2(ka, kb);

    // ---- V ----
    float2 v2 = *(const float2*)(row + 2 * CC + h * 64 + d0);
    *(float2*)(g_v + ((size_t)h * TT + t) * 64 + d0) =
        make_float2(v2.x * 0.5f, v2.y * 0.5f);
}

// ---------------------------------------------------------------------------
// Sliding-window flash attention, fp32. 64x64 tiles, online softmax.
// ---------------------------------------------------------------------------
__global__ void attn_win()
{
    extern __shared__ float sm[];
    float* Qs = sm;                 // [64][68] transposed: Qs[d][r]
    float* Ks = Qs + 64 * 68;       // [64][68] transposed: Ks[d][n]
    float* Vs = Ks + 64 * 68;       // [64][64] natural:    Vs[n][c]
    float* Ps = Vs + 64 * 64;       // [64][68] transposed: Ps[n][r]

    const int h  = blockIdx.y;
    const int qb = blockIdx.x;
    const int t0 = qb * 64;
    const float* Qg = g_q + ((size_t)h * TT + t0) * 64;
    const float* Kg = g_k + (size_t)h * TT * 64;
    const float* Vg = g_v + (size_t)h * TT * 64;

    const int tid = threadIdx.x;
    const int tx = tid & 15, ty = tid >> 4;

    #pragma unroll
    for (int it = 0; it < 4; it++) {
        int idx = tid + it * 256;
        int r = idx >> 4, g = (idx & 15) * 4;
        float4 v = *(const float4*)(Qg + r * 64 + g);
        Qs[(g + 0) * 68 + r] = v.x; Qs[(g + 1) * 68 + r] = v.y;
        Qs[(g + 2) * 68 + r] = v.z; Qs[(g + 3) * 68 + r] = v.w;
    }

    float o[4][4];
    float mi[4], li[4];
    #pragma unroll
    for (int i = 0; i < 4; i++) {
        mi[i] = -1e30f; li[i] = 0.f;
        #pragma unroll
        for (int j = 0; j < 4; j++) o[i][j] = 0.f;
    }

    const int jb0 = (qb >= 16) ? (qb - 16) : 0;
    for (int jb = jb0; jb <= qb; jb++) {
        const int s0 = jb * 64;
        __syncthreads();
        #pragma unroll
        for (int it = 0; it < 4; it++) {
            int idx = tid + it * 256;
            int r = idx >> 4, g = (idx & 15) * 4;
            float4 kv = *(const float4*)(Kg + (size_t)(s0 + r) * 64 + g);
            Ks[(g + 0) * 68 + r] = kv.x; Ks[(g + 1) * 68 + r] = kv.y;
            Ks[(g + 2) * 68 + r] = kv.z; Ks[(g + 3) * 68 + r] = kv.w;
            float4 vv = *(const float4*)(Vg + (size_t)(s0 + r) * 64 + g);
            *(float4*)&Vs[r * 64 + g] = vv;
        }
        __syncthreads();

        float s[4][4];
        #pragma unroll
        for (int i = 0; i < 4; i++)
            #pragma unroll
            for (int j = 0; j < 4; j++) s[i][j] = 0.f;
        #pragma unroll
        for (int dd = 0; dd < 64; dd++) {
            float4 a = *(const float4*)&Qs[dd * 68 + ty * 4];
            float4 b = *(const float4*)&Ks[dd * 68 + tx * 4];
            float aa[4] = {a.x, a.y, a.z, a.w};
            float bb[4] = {b.x, b.y, b.z, b.w};
            #pragma unroll
            for (int i = 0; i < 4; i++)
                #pragma unroll
                for (int j = 0; j < 4; j++) s[i][j] += aa[i] * bb[j];
        }

        #pragma unroll
        for (int i = 0; i < 4; i++) {
            int rg = t0 + ty * 4 + i;
            #pragma unroll
            for (int j = 0; j < 4; j++) {
                int cg = s0 + tx * 4 + j;
                int diff = rg - cg;
                s[i][j] = (diff >= 0 && diff < WIN) ? s[i][j] * SCALE_F : -1e30f;
            }
        }

        #pragma unroll
        for (int i = 0; i < 4; i++) {
            float tm = fmaxf(fmaxf(s[i][0], s[i][1]), fmaxf(s[i][2], s[i][3]));
            #pragma unroll
            for (int off = 8; off; off >>= 1)
                tm = fmaxf(tm, __shfl_xor_sync(0xffffffffu, tm, off));
            float mn = fmaxf(mi[i], tm);
            float alpha = __expf(mi[i] - mn);
            float rs = 0.f;
            #pragma unroll
            for (int j = 0; j < 4; j++) {
                s[i][j] = __expf(s[i][j] - mn);
                rs += s[i][j];
            }
            #pragma unroll
            for (int off = 8; off; off >>= 1)
                rs += __shfl_xor_sync(0xffffffffu, rs, off);
            li[i] = li[i] * alpha + rs;
            mi[i] = mn;
            #pragma unroll
            for (int j = 0; j < 4; j++) o[i][j] *= alpha;
        }

        #pragma unroll
        for (int j = 0; j < 4; j++)
            #pragma unroll
            for (int i = 0; i < 4; i++)
                Ps[(tx * 4 + j) * 68 + ty * 4 + i] = s[i][j];
        __syncthreads();

        #pragma unroll
        for (int n = 0; n < 64; n++) {
            float4 a = *(const float4*)&Ps[n * 68 + ty * 4];
            float4 b = *(const float4*)&Vs[n * 64 + tx * 4];
            float aa[4] = {a.x, a.y, a.z, a.w};
            float bb[4] = {b.x, b.y, b.z, b.w};
            #pragma unroll
            for (int i = 0; i < 4; i++)
                #pragma unroll
                for (int j = 0; j < 4; j++) o[i][j] += aa[i] * bb[j];
        }
    }

    #pragma unroll
    for (int i = 0; i < 4; i++) {
        float inv = 1.f / li[i];
        float* out = g_att + (size_t)(t0 + ty * 4 + i) * CC + h * 64 + tx * 4;
        *(float4*)out = make_float4(o[i][0] * inv, o[i][1] * inv,
                                    o[i][2] * inv, o[i][3] * inv);
    }
}

// ---------------------------------------------------------------------------
extern "C" void kernel_launch(void* const* d_in, const int* in_sizes, int n_in,
                              void* d_out, int out_size)
{
    const float* x    = (const float*)d_in[0];
    // d_in[1]=tokens (unused), d_in[2]=pos (identity, unused)
    const float* wqkv = (const float*)d_in[3];
    const float* wo   = (const float*)d_in[4];
    const float* qnw  = (const float*)d_in[5];
    const float* knw  = (const float*)d_in[6];
    const float* cosT = (const float*)d_in[7];
    const float* sinT = (const float*)d_in[8];
    float* out = (float*)d_out;

    float *p_qkv = nullptr, *p_att = nullptr;
    cudaGetSymbolAddress((void**)&p_qkv, g_qkv);
    cudaGetSymbolAddress((void**)&p_att, g_att);

    // 1) qkv = x @ w_qkv^T   (4096 x 3072, K=1024) — tensor pipe (mma.sync tf32)
    gemm_mma<<<dim3(3072 / 128, 4096 / 128), 256>>>(x, wqkv, p_qkv, TT, 3 * CC, CC);

    // 2) rmsnorm + rope + v*0.5, scatter to [H][T][64]
    qkv_post<<<TT, 512>>>(cosT, sinT, qnw, knw);

    // 3) sliding-window attention -> g_att (4096 x 1024, head-concat layout)
    size_t smem = (size_t)(64 * 68 * 3 + 64 * 64) * sizeof(float);  // 68608 B
    cudaFuncSetAttribute(attn_win, cudaFuncAttributeMaxDynamicSharedMemorySize, (int)smem);
    attn_win<<<dim3(TT / 64, HH), 256, smem>>>();

    // 4) out = att @ w_o^T   (4096 x 1024, K=1024) — tensor pipe (mma.sync tf32)
    gemm_mma<<<dim3(1024 / 128, 4096 / 128), 256>>>(p_att, wo, out, TT, CC, CC);
}

// round 9
// speedup vs baseline: 3.1138x; 1.7663x over previous
#include <cuda_runtime.h>
#include <cuda_bf16.h>
#include <cstdint>
#include <math.h>

#define TT   4096
#define CC   1024
#define HH   16
#define DD   64
#define WIN  1024
#define SCALE_F 0.12f

// scratch (allocation-free contract: __device__ globals)
__device__ float g_qkv[TT * 3 * CC];   // 48 MB
__device__ float g_q[HH * TT * DD];    // 16 MB
__device__ float g_k[HH * TT * DD];
__device__ float g_v[HH * TT * DD];
__device__ float g_att[TT * CC];       // 16 MB

__device__ __forceinline__ uint32_t f2tf(float f) {
    uint32_t u;
    asm("cvt.rn.tf32.f32 %0, %1;" : "=r"(u) : "f"(f));
    return u;
}

__device__ __forceinline__ void mma_tf32_16n8k8(float* c, const uint32_t* a,
                                                const uint32_t* b) {
    asm volatile(
        "mma.sync.aligned.m16n8k8.row.col.f32.tf32.tf32.f32 "
        "{%0,%1,%2,%3}, {%4,%5,%6,%7}, {%8,%9}, {%0,%1,%2,%3};"
        : "+f"(c[0]), "+f"(c[1]), "+f"(c[2]), "+f"(c[3])
        : "r"(a[0]), "r"(a[1]), "r"(a[2]), "r"(a[3]), "r"(b[0]), "r"(b[1]));
}

// ===========================================================================
// C[M,N] = A[M,K] * B[N,K]^T  via mma.sync tf32 (tensor pipe, base sm_103).
// ===========================================================================
#define SSTR 36

__global__ __launch_bounds__(256, 2)
void gemm_mma(const float* __restrict__ A, const float* __restrict__ B,
              float* __restrict__ C, int M, int N, int K)
{
    __shared__ uint32_t As[128 * SSTR];
    __shared__ uint32_t Bs[128 * SSTR];

    const int tid = threadIdx.x;
    const int wid = tid >> 5, lid = tid & 31;
    const int g = lid >> 2, t = lid & 3;
    const int wm = wid >> 1, wn = wid & 1;
    const int bm = blockIdx.y * 128, bn = blockIdx.x * 128;

    float acc[2][8][4];
    #pragma unroll
    for (int i = 0; i < 2; i++)
        #pragma unroll
        for (int j = 0; j < 8; j++)
            #pragma unroll
            for (int l = 0; l < 4; l++) acc[i][j][l] = 0.f;

    for (int c0 = 0; c0 < K; c0 += 32) {
        __syncthreads();
        const float* Ag = A + (size_t)bm * K + c0;
        const float* Bg = B + (size_t)bn * K + c0;
        #pragma unroll
        for (int i = 0; i < 4; i++) {
            int idx = tid + i * 256;
            int row = idx >> 3, c4 = (idx & 7) * 4;
            float4 a = *(const float4*)(Ag + (size_t)row * K + c4);
            float4 b = *(const float4*)(Bg + (size_t)row * K + c4);
            *(uint4*)&As[row * SSTR + c4] =
                make_uint4(f2tf(a.x), f2tf(a.y), f2tf(a.z), f2tf(a.w));
            *(uint4*)&Bs[row * SSTR + c4] =
                make_uint4(f2tf(b.x), f2tf(b.y), f2tf(b.z), f2tf(b.w));
        }
        __syncthreads();

        #pragma unroll
        for (int ks = 0; ks < 4; ks++) {
            const int kb = ks * 8;
            uint32_t af[2][4];
            #pragma unroll
            for (int mt = 0; mt < 2; mt++) {
                int r0 = wm * 32 + mt * 16 + g;
                af[mt][0] = As[(r0    ) * SSTR + kb + t];
                af[mt][1] = As[(r0 + 8) * SSTR + kb + t];
                af[mt][2] = As[(r0    ) * SSTR + kb + t + 4];
                af[mt][3] = As[(r0 + 8) * SSTR + kb + t + 4];
            }
            uint32_t bf[8][2];
            #pragma unroll
            for (int nt = 0; nt < 8; nt++) {
                int n0 = wn * 64 + nt * 8 + g;
                bf[nt][0] = Bs[n0 * SSTR + kb + t];
                bf[nt][1] = Bs[n0 * SSTR + kb + t + 4];
            }
            #pragma unroll
            for (int mt = 0; mt < 2; mt++)
                #pragma unroll
                for (int nt = 0; nt < 8; nt++)
                    mma_tf32_16n8k8(acc[mt][nt], af[mt], bf[nt]);
        }
    }

    #pragma unroll
    for (int mt = 0; mt < 2; mt++) {
        int row0 = bm + wm * 32 + mt * 16 + g;
        #pragma unroll
        for (int nt = 0; nt < 8; nt++) {
            int col = bn + wn * 64 + nt * 8 + 2 * t;
            *(float2*)(C + (size_t)row0 * N + col) =
                make_float2(acc[mt][nt][0], acc[mt][nt][1]);
            *(float2*)(C + (size_t)(row0 + 8) * N + col) =
                make_float2(acc[mt][nt][2], acc[mt][nt][3]);
        }
    }
}

// ---------------------------------------------------------------------------
// Split qkv row into per-head Q/K/V with RMSNorm + RoPE (Q,K) and 0.5*V.
// ---------------------------------------------------------------------------
__global__ void qkv_post(const float* __restrict__ cosT, const float* __restrict__ sinT,
                         const float* __restrict__ qw, const float* __restrict__ kw)
{
    const int t    = blockIdx.x;
    const int h    = threadIdx.x >> 5;
    const int lane = threadIdx.x & 31;
    const int d0   = lane * 2;
    const float* row = g_qkv + (size_t)t * (3 * CC);

    float cv = 0.f, sv = 0.f;
    if (lane < 16) { cv = cosT[t * 16 + lane]; sv = sinT[t * 16 + lane]; }

    float2 q2 = *(const float2*)(row + h * 64 + d0);
    float ss = q2.x * q2.x + q2.y * q2.y;
    #pragma unroll
    for (int off = 16; off; off >>= 1) ss += __shfl_xor_sync(0xffffffffu, ss, off);
    float rn = rsqrtf(ss * (1.f / 64.f) + 1e-6f);
    float qa = q2.x * rn * qw[d0];
    float qb = q2.y * rn * qw[d0 + 1];
    if (lane < 16) {
        float e = qa, od = qb;
        qa = e * cv - od * sv;
        qb = e * sv + od * cv;
    }
    *(float2*)(g_q + ((size_t)h * TT + t) * 64 + d0) = make_float2(qa, qb);

    float2 k2 = *(const float2*)(row + CC + h * 64 + d0);
    float ssk = k2.x * k2.x + k2.y * k2.y;
    #pragma unroll
    for (int off = 16; off; off >>= 1) ssk += __shfl_xor_sync(0xffffffffu, ssk, off);
    float rk = rsqrtf(ssk * (1.f / 64.f) + 1e-6f);
    float ka = k2.x * rk * kw[d0];
    float kb = k2.y * rk * kw[d0 + 1];
    if (lane < 16) {
        float e = ka, od = kb;
        ka = e * cv - od * sv;
        kb = e * sv + od * cv;
    }
    *(float2*)(g_k + ((size_t)h * TT + t) * 64 + d0) = make_float2(ka, kb);

    float2 v2 = *(const float2*)(row + 2 * CC + h * 64 + d0);
    *(float2*)(g_v + ((size_t)h * TT + t) * 64 + d0) =
        make_float2(v2.x * 0.5f, v2.y * 0.5f);
}

// ===========================================================================
// Sliding-window flash attention on tensor pipe (mma.sync tf32).
// CTA: 128 queries x 1 head. 256 threads = 8 warps, warp owns 16 rows.
// Key blocks of 64. Online softmax in registers (quad shfl reductions).
// smem (tf32/u32): Qs[128][68], Ps[128][68], Ks[64][68], Vs[64][72]
// ===========================================================================
#define QSTR 68
#define VSTR 72
#define ATT_SMEM ((128 * QSTR + 128 * QSTR + 64 * QSTR + 64 * VSTR) * 4)

__global__ __launch_bounds__(256, 2)
void attn_mma()
{
    extern __shared__ uint32_t sm4[];
    uint32_t* Qs = sm4;                   // [128][68]
    uint32_t* Ps = Qs + 128 * QSTR;       // [128][68]
    uint32_t* Ks = Ps + 128 * QSTR;       // [64][68]
    uint32_t* Vs = Ks + 64 * QSTR;        // [64][72]

    const int h  = blockIdx.y;
    const int qb = blockIdx.x;
    const int t0 = qb * 128;
    const int tid = threadIdx.x;
    const int wid = tid >> 5, lid = tid & 31;
    const int g = lid >> 2, t = lid & 3;
    const int r0 = wid * 16;

    const float* Qg = g_q + ((size_t)h * TT + t0) * 64;
    const float* Kg = g_k + (size_t)h * TT * 64;
    const float* Vg = g_v + (size_t)h * TT * 64;

    // stage Q as tf32 (rows=query, cols=d)
    #pragma unroll
    for (int i = 0; i < 8; i++) {
        int idx = tid + i * 256;
        int r = idx >> 4, c4 = (idx & 15) * 4;
        float4 v = *(const float4*)(Qg + (size_t)r * 64 + c4);
        *(uint4*)&Qs[r * QSTR + c4] =
            make_uint4(f2tf(v.x), f2tf(v.y), f2tf(v.z), f2tf(v.w));
    }

    float o[8][4];
    #pragma unroll
    for (int nt = 0; nt < 8; nt++)
        #pragma unroll
        for (int l = 0; l < 4; l++) o[nt][l] = 0.f;
    float mi0 = -1e30f, mi1 = -1e30f, li0 = 0.f, li1 = 0.f;

    const int rg0 = t0 + r0 + g, rg1 = rg0 + 8;

    int jb_lo = 2 * qb - 16; if (jb_lo < 0) jb_lo = 0;
    const int jb_hi = 2 * qb + 1;

    for (int jb = jb_lo; jb <= jb_hi; jb++) {
        const int s0 = jb * 64;
        __syncthreads();   // prev iter's PV done; Q staged (first iter)
        #pragma unroll
        for (int i = 0; i < 4; i++) {
            int idx = tid + i * 256;
            int r = idx >> 4, c4 = (idx & 15) * 4;
            float4 kv = *(const float4*)(Kg + (size_t)(s0 + r) * 64 + c4);
            *(uint4*)&Ks[r * QSTR + c4] =
                make_uint4(f2tf(kv.x), f2tf(kv.y), f2tf(kv.z), f2tf(kv.w));
            float4 vv = *(const float4*)(Vg + (size_t)(s0 + r) * 64 + c4);
            *(uint4*)&Vs[r * VSTR + c4] =
                make_uint4(f2tf(vv.x), f2tf(vv.y), f2tf(vv.z), f2tf(vv.w));
        }
        __syncthreads();

        // ---- S = Q K^T (warp rows r0..r0+15, all 64 keys) ----
        float s[8][4];
        #pragma unroll
        for (int nt = 0; nt < 8; nt++)
            #pragma unroll
            for (int l = 0; l < 4; l++) s[nt][l] = 0.f;
        #pragma unroll
        for (int ks = 0; ks < 8; ks++) {
            const int kb = ks * 8;
            uint32_t a[4];
            a[0] = Qs[(r0 + g    ) * QSTR + kb + t];
            a[1] = Qs[(r0 + g + 8) * QSTR + kb + t];
            a[2] = Qs[(r0 + g    ) * QSTR + kb + t + 4];
            a[3] = Qs[(r0 + g + 8) * QSTR + kb + t + 4];
            #pragma unroll
            for (int nt = 0; nt < 8; nt++) {
                uint32_t b[2];
                b[0] = Ks[(nt * 8 + g) * QSTR + kb + t];
                b[1] = Ks[(nt * 8 + g) * QSTR + kb + t + 4];
                mma_tf32_16n8k8(s[nt], a, b);
            }
        }

        // ---- scale + window mask ----
        float tm0 = -1e30f, tm1 = -1e30f;
        #pragma unroll
        for (int nt = 0; nt < 8; nt++) {
            int cg = s0 + nt * 8 + 2 * t;
            int d00 = rg0 - cg, d01 = d00 - 1;
            int d10 = rg1 - cg, d11 = d10 - 1;
            s[nt][0] = (d00 >= 0 && d00 < WIN) ? s[nt][0] * SCALE_F : -1e30f;
            s[nt][1] = (d01 >= 0 && d01 < WIN) ? s[nt][1] * SCALE_F : -1e30f;
            s[nt][2] = (d10 >= 0 && d10 < WIN) ? s[nt][2] * SCALE_F : -1e30f;
            s[nt][3] = (d11 >= 0 && d11 < WIN) ? s[nt][3] * SCALE_F : -1e30f;
            tm0 = fmaxf(tm0, fmaxf(s[nt][0], s[nt][1]));
            tm1 = fmaxf(tm1, fmaxf(s[nt][2], s[nt][3]));
        }
        tm0 = fmaxf(tm0, __shfl_xor_sync(0xffffffffu, tm0, 1));
        tm0 = fmaxf(tm0, __shfl_xor_sync(0xffffffffu, tm0, 2));
        tm1 = fmaxf(tm1, __shfl_xor_sync(0xffffffffu, tm1, 1));
        tm1 = fmaxf(tm1, __shfl_xor_sync(0xffffffffu, tm1, 2));

        // ---- online softmax ----
        float mn0 = fmaxf(mi0, tm0), mn1 = fmaxf(mi1, tm1);
        float al0 = __expf(mi0 - mn0), al1 = __expf(mi1 - mn1);
        mi0 = mn0; mi1 = mn1;
        float rs0 = 0.f, rs1 = 0.f;
        #pragma unroll
        for (int nt = 0; nt < 8; nt++) {
            float p00 = __expf(s[nt][0] - mn0);
            float p01 = __expf(s[nt][1] - mn0);
            float p10 = __expf(s[nt][2] - mn1);
            float p11 = __expf(s[nt][3] - mn1);
            rs0 += p00 + p01;
            rs1 += p10 + p11;
            int col = nt * 8 + 2 * t;
            *(uint2*)&Ps[(r0 + g    ) * QSTR + col] = make_uint2(f2tf(p00), f2tf(p01));
            *(uint2*)&Ps[(r0 + g + 8) * QSTR + col] = make_uint2(f2tf(p10), f2tf(p11));
            o[nt][0] *= al0; o[nt][1] *= al0;
            o[nt][2] *= al1; o[nt][3] *= al1;
        }
        rs0 += __shfl_xor_sync(0xffffffffu, rs0, 1);
        rs0 += __shfl_xor_sync(0xffffffffu, rs0, 2);
        rs1 += __shfl_xor_sync(0xffffffffu, rs1, 1);
        rs1 += __shfl_xor_sync(0xffffffffu, rs1, 2);
        li0 = li0 * al0 + rs0;
        li1 = li1 * al1 + rs1;
        __syncwarp();

        // ---- O += P V  (A=P rows warp-local, B=V^T via transposed index) ----
        #pragma unroll
        for (int ks = 0; ks < 8; ks++) {
            const int kb = ks * 8;
            uint32_t a[4];
            a[0] = Ps[(r0 + g    ) * QSTR + kb + t];
            a[1] = Ps[(r0 + g + 8) * QSTR + kb + t];
            a[2] = Ps[(r0 + g    ) * QSTR + kb + t + 4];
            a[3] = Ps[(r0 + g + 8) * QSTR + kb + t + 4];
            #pragma unroll
            for (int nt = 0; nt < 8; nt++) {
                uint32_t b[2];
                b[0] = Vs[(kb + t    ) * VSTR + nt * 8 + g];
                b[1] = Vs[(kb + t + 4) * VSTR + nt * 8 + g];
                mma_tf32_16n8k8(o[nt], a, b);
            }
        }
    }

    // ---- epilogue: normalize and write head-concat layout ----
    float inv0 = 1.f / li0, inv1 = 1.f / li1;
    #pragma unroll
    for (int nt = 0; nt < 8; nt++) {
        int col = h * 64 + nt * 8 + 2 * t;
        *(float2*)(g_att + (size_t)rg0 * CC + col) =
            make_float2(o[nt][0] * inv0, o[nt][1] * inv0);
        *(float2*)(g_att + (size_t)rg1 * CC + col) =
            make_float2(o[nt][2] * inv1, o[nt][3] * inv1);
    }
}

// ---------------------------------------------------------------------------
extern "C" void kernel_launch(void* const* d_in, const int* in_sizes, int n_in,
                              void* d_out, int out_size)
{
    const float* x    = (const float*)d_in[0];
    const float* wqkv = (const float*)d_in[3];
    const float* wo   = (const float*)d_in[4];
    const float* qnw  = (const float*)d_in[5];
    const float* knw  = (const float*)d_in[6];
    const float* cosT = (const float*)d_in[7];
    const float* sinT = (const float*)d_in[8];
    float* out = (float*)d_out;

    float *p_qkv = nullptr, *p_att = nullptr;
    cudaGetSymbolAddress((void**)&p_qkv, g_qkv);
    cudaGetSymbolAddress((void**)&p_att, g_att);

    // 1) qkv = x @ w_qkv^T — tensor pipe (mma.sync tf32)
    gemm_mma<<<dim3(3072 / 128, 4096 / 128), 256>>>(x, wqkv, p_qkv, TT, 3 * CC, CC);

    // 2) rmsnorm + rope + v*0.5, scatter to [H][T][64]
    qkv_post<<<TT, 512>>>(cosT, sinT, qnw, knw);

    // 3) sliding-window attention — tensor pipe (mma.sync tf32)
    cudaFuncSetAttribute(attn_mma, cudaFuncAttributeMaxDynamicSharedMemorySize, ATT_SMEM);
    attn_mma<<<dim3(TT / 128, HH), 256, ATT_SMEM>>>();

    // 4) out = att @ w_o^T — tensor pipe (mma.sync tf32)
    gemm_mma<<<dim3(1024 / 128, 4096 / 128), 256>>>(p_att, wo, out, TT, CC, CC);
}

// round 10
// speedup vs baseline: 3.1379x; 1.0077x over previous
#include <cuda_runtime.h>
#include <cuda_bf16.h>
#include <cstdint>
#include <math.h>

#define TT   4096
#define CC   1024
#define HH   16
#define DD   64
#define WIN  1024
#define SCALE_F 0.12f

// scratch (allocation-free contract: __device__ globals)
__device__ float    g_qkv[TT * 3 * CC];     // fp32 qkv projection output
__device__ uint32_t g_q[HH * TT * DD];      // tf32 bit patterns
__device__ uint32_t g_k[HH * TT * DD];
__device__ uint32_t g_v[HH * TT * DD];
__device__ uint32_t g_att[TT * CC];         // tf32 attention output
__device__ uint32_t g_xt[TT * CC];          // tf32 x
__device__ uint32_t g_wqkvt[3 * CC * CC];   // tf32 w_qkv
__device__ uint32_t g_wot[CC * CC];         // tf32 w_o

__device__ __forceinline__ uint32_t f2tf(float f) {
    uint32_t u;
    asm("cvt.rn.tf32.f32 %0, %1;" : "=r"(u) : "f"(f));
    return u;
}

__device__ __forceinline__ void mma_tf32_16n8k8(float* c, const uint32_t* a,
                                                const uint32_t* b) {
    asm volatile(
        "mma.sync.aligned.m16n8k8.row.col.f32.tf32.tf32.f32 "
        "{%0,%1,%2,%3}, {%4,%5,%6,%7}, {%8,%9}, {%0,%1,%2,%3};"
        : "+f"(c[0]), "+f"(c[1]), "+f"(c[2]), "+f"(c[3])
        : "r"(a[0]), "r"(a[1]), "r"(a[2]), "r"(a[3]), "r"(b[0]), "r"(b[1]));
}

__device__ __forceinline__ void cpasync16(uint32_t saddr, const void* g) {
    asm volatile("cp.async.cg.shared.global [%0], [%1], 16;"
                 :: "r"(saddr), "l"(g) : "memory");
}
#define CP_COMMIT() asm volatile("cp.async.commit_group;" ::: "memory")
#define CP_WAIT0()  asm volatile("cp.async.wait_group 0;" ::: "memory")

// ---------------------------------------------------------------------------
// fp32 -> tf32 bulk convert
// ---------------------------------------------------------------------------
__global__ void cvt_tf32_k(const float4* __restrict__ in, uint4* __restrict__ out,
                           int n4)
{
    int i = blockIdx.x * 256 + threadIdx.x;
    if (i < n4) {
        float4 v = in[i];
        out[i] = make_uint4(f2tf(v.x), f2tf(v.y), f2tf(v.z), f2tf(v.w));
    }
}

// ===========================================================================
// C[M,N] = A[M,K] * B[N,K]^T, A/B already tf32 in global.
// cp.async double-buffered, 128x128 CTA tile, K-chunk 32, 256 thr / 8 warps.
// ===========================================================================
#define SSTR  36
#define CHUNK (128 * SSTR)   // u32 per operand buffer

__global__ __launch_bounds__(256, 2)
void gemm_mma(const uint32_t* __restrict__ A, const uint32_t* __restrict__ B,
              float* __restrict__ C, int M, int N, int K)
{
    extern __shared__ uint32_t smg[];   // [2 buffers][A CHUNK | B CHUNK]

    const int tid = threadIdx.x;
    const int wid = tid >> 5, lid = tid & 31;
    const int g = lid >> 2, t = lid & 3;
    const int wm = wid >> 1, wn = wid & 1;
    const int bm = blockIdx.y * 128, bn = blockIdx.x * 128;

    const int srow = tid >> 3, sc4 = (tid & 7) * 4;   // staging coords (x4 iters)

    float acc[2][8][4];
    #pragma unroll
    for (int i = 0; i < 2; i++)
        #pragma unroll
        for (int j = 0; j < 8; j++)
            #pragma unroll
            for (int l = 0; l < 4; l++) acc[i][j][l] = 0.f;

    const uint32_t* Agb = A + (size_t)bm * K;
    const uint32_t* Bgb = B + (size_t)bn * K;

    // prologue: issue chunk 0 into buffer 0
    {
        uint32_t sA = (uint32_t)__cvta_generic_to_shared(smg);
        uint32_t sB = sA + CHUNK * 4;
        #pragma unroll
        for (int i = 0; i < 4; i++) {
            int row = srow + i * 32;
            uint32_t so = (uint32_t)(row * SSTR + sc4) * 4;
            cpasync16(sA + so, Agb + (size_t)row * K + sc4);
            cpasync16(sB + so, Bgb + (size_t)row * K + sc4);
        }
        CP_COMMIT();
    }

    const int nc = K / 32;
    int buf = 0;
    for (int c = 0; c < nc; c++) {
        CP_WAIT0();
        __syncthreads();   // chunk c visible; all warps done with chunk c-1's buffer

        if (c + 1 < nc) {  // issue chunk c+1 into the other buffer
            uint32_t sA = (uint32_t)__cvta_generic_to_shared(smg) +
                          (buf ^ 1) * 2 * CHUNK * 4;
            uint32_t sB = sA + CHUNK * 4;
            const uint32_t* Ag = Agb + (c + 1) * 32;
            const uint32_t* Bg = Bgb + (c + 1) * 32;
            #pragma unroll
            for (int i = 0; i < 4; i++) {
                int row = srow + i * 32;
                uint32_t so = (uint32_t)(row * SSTR + sc4) * 4;
                cpasync16(sA + so, Ag + (size_t)row * K + sc4);
                cpasync16(sB + so, Bg + (size_t)row * K + sc4);
            }
            CP_COMMIT();
        }

        const uint32_t* As = smg + buf * 2 * CHUNK;
        const uint32_t* Bs = As + CHUNK;
        #pragma unroll
        for (int ks = 0; ks < 4; ks++) {
            const int kb = ks * 8;
            uint32_t af[2][4];
            #pragma unroll
            for (int mt = 0; mt < 2; mt++) {
                int r0 = wm * 32 + mt * 16 + g;
                af[mt][0] = As[(r0    ) * SSTR + kb + t];
                af[mt][1] = As[(r0 + 8) * SSTR + kb + t];
                af[mt][2] = As[(r0    ) * SSTR + kb + t + 4];
                af[mt][3] = As[(r0 + 8) * SSTR + kb + t + 4];
            }
            uint32_t bf[8][2];
            #pragma unroll
            for (int nt = 0; nt < 8; nt++) {
                int n0 = wn * 64 + nt * 8 + g;
                bf[nt][0] = Bs[n0 * SSTR + kb + t];
                bf[nt][1] = Bs[n0 * SSTR + kb + t + 4];
            }
            #pragma unroll
            for (int mt = 0; mt < 2; mt++)
                #pragma unroll
                for (int nt = 0; nt < 8; nt++)
                    mma_tf32_16n8k8(acc[mt][nt], af[mt], bf[nt]);
        }
        buf ^= 1;
    }

    #pragma unroll
    for (int mt = 0; mt < 2; mt++) {
        int row0 = bm + wm * 32 + mt * 16 + g;
        #pragma unroll
        for (int nt = 0; nt < 8; nt++) {
            int col = bn + wn * 64 + nt * 8 + 2 * t;
            *(float2*)(C + (size_t)row0 * N + col) =
                make_float2(acc[mt][nt][0], acc[mt][nt][1]);
            *(float2*)(C + (size_t)(row0 + 8) * N + col) =
                make_float2(acc[mt][nt][2], acc[mt][nt][3]);
        }
    }
}

// ---------------------------------------------------------------------------
// Split qkv row into per-head Q/K/V with RMSNorm + RoPE (Q,K) and 0.5*V.
// Outputs stored as tf32 bit patterns.
// ---------------------------------------------------------------------------
__global__ void qkv_post(const float* __restrict__ cosT, const float* __restrict__ sinT,
                         const float* __restrict__ qw, const float* __restrict__ kw)
{
    const int t    = blockIdx.x;
    const int h    = threadIdx.x >> 5;
    const int lane = threadIdx.x & 31;
    const int d0   = lane * 2;
    const float* row = g_qkv + (size_t)t * (3 * CC);

    float cv = 0.f, sv = 0.f;
    if (lane < 16) { cv = cosT[t * 16 + lane]; sv = sinT[t * 16 + lane]; }

    float2 q2 = *(const float2*)(row + h * 64 + d0);
    float ss = q2.x * q2.x + q2.y * q2.y;
    #pragma unroll
    for (int off = 16; off; off >>= 1) ss += __shfl_xor_sync(0xffffffffu, ss, off);
    float rn = rsqrtf(ss * (1.f / 64.f) + 1e-6f);
    float qa = q2.x * rn * qw[d0];
    float qb = q2.y * rn * qw[d0 + 1];
    if (lane < 16) {
        float e = qa, od = qb;
        qa = e * cv - od * sv;
        qb = e * sv + od * cv;
    }
    *(uint2*)(g_q + ((size_t)h * TT + t) * 64 + d0) = make_uint2(f2tf(qa), f2tf(qb));

    float2 k2 = *(const float2*)(row + CC + h * 64 + d0);
    float ssk = k2.x * k2.x + k2.y * k2.y;
    #pragma unroll
    for (int off = 16; off; off >>= 1) ssk += __shfl_xor_sync(0xffffffffu, ssk, off);
    float rk = rsqrtf(ssk * (1.f / 64.f) + 1e-6f);
    float ka = k2.x * rk * kw[d0];
    float kb = k2.y * rk * kw[d0 + 1];
    if (lane < 16) {
        float e = ka, od = kb;
        ka = e * cv - od * sv;
        kb = e * sv + od * cv;
    }
    *(uint2*)(g_k + ((size_t)h * TT + t) * 64 + d0) = make_uint2(f2tf(ka), f2tf(kb));

    float2 v2 = *(const float2*)(row + 2 * CC + h * 64 + d0);
    *(uint2*)(g_v + ((size_t)h * TT + t) * 64 + d0) =
        make_uint2(f2tf(v2.x * 0.5f), f2tf(v2.y * 0.5f));
}

// ===========================================================================
// Sliding-window flash attention on tensor pipe (mma.sync tf32).
// Q/K/V already tf32 in global; output written as tf32 for the O-proj GEMM.
// ===========================================================================
#define QSTR 68
#define VSTR 72
#define ATT_SMEM ((128 * QSTR + 128 * QSTR + 64 * QSTR + 64 * VSTR) * 4)

__global__ __launch_bounds__(256, 2)
void attn_mma()
{
    extern __shared__ uint32_t sm4[];
    uint32_t* Qs = sm4;                   // [128][68]
    uint32_t* Ps = Qs + 128 * QSTR;       // [128][68]
    uint32_t* Ks = Ps + 128 * QSTR;       // [64][68]
    uint32_t* Vs = Ks + 64 * QSTR;        // [64][72]

    const int h  = blockIdx.y;
    const int qb = blockIdx.x;
    const int t0 = qb * 128;
    const int tid = threadIdx.x;
    const int wid = tid >> 5, lid = tid & 31;
    const int g = lid >> 2, t = lid & 3;
    const int r0 = wid * 16;

    const uint32_t* Qg = g_q + ((size_t)h * TT + t0) * 64;
    const uint32_t* Kg = g_k + (size_t)h * TT * 64;
    const uint32_t* Vg = g_v + (size_t)h * TT * 64;

    #pragma unroll
    for (int i = 0; i < 8; i++) {
        int idx = tid + i * 256;
        int r = idx >> 4, c4 = (idx & 15) * 4;
        *(uint4*)&Qs[r * QSTR + c4] = *(const uint4*)(Qg + (size_t)r * 64 + c4);
    }

    float o[8][4];
    #pragma unroll
    for (int nt = 0; nt < 8; nt++)
        #pragma unroll
        for (int l = 0; l < 4; l++) o[nt][l] = 0.f;
    float mi0 = -1e30f, mi1 = -1e30f, li0 = 0.f, li1 = 0.f;

    const int rg0 = t0 + r0 + g, rg1 = rg0 + 8;

    int jb_lo = 2 * qb - 16; if (jb_lo < 0) jb_lo = 0;
    const int jb_hi = 2 * qb + 1;

    for (int jb = jb_lo; jb <= jb_hi; jb++) {
        const int s0 = jb * 64;
        __syncthreads();
        #pragma unroll
        for (int i = 0; i < 4; i++) {
            int idx = tid + i * 256;
            int r = idx >> 4, c4 = (idx & 15) * 4;
            *(uint4*)&Ks[r * QSTR + c4] = *(const uint4*)(Kg + (size_t)(s0 + r) * 64 + c4);
            *(uint4*)&Vs[r * VSTR + c4] = *(const uint4*)(Vg + (size_t)(s0 + r) * 64 + c4);
        }
        __syncthreads();

        float s[8][4];
        #pragma unroll
        for (int nt = 0; nt < 8; nt++)
            #pragma unroll
            for (int l = 0; l < 4; l++) s[nt][l] = 0.f;
        #pragma unroll
        for (int ks = 0; ks < 8; ks++) {
            const int kb = ks * 8;
            uint32_t a[4];
            a[0] = Qs[(r0 + g    ) * QSTR + kb + t];
            a[1] = Qs[(r0 + g + 8) * QSTR + kb + t];
            a[2] = Qs[(r0 + g    ) * QSTR + kb + t + 4];
            a[3] = Qs[(r0 + g + 8) * QSTR + kb + t + 4];
            #pragma unroll
            for (int nt = 0; nt < 8; nt++) {
                uint32_t b[2];
                b[0] = Ks[(nt * 8 + g) * QSTR + kb + t];
                b[1] = Ks[(nt * 8 + g) * QSTR + kb + t + 4];
                mma_tf32_16n8k8(s[nt], a, b);
            }
        }

        float tm0 = -1e30f, tm1 = -1e30f;
        #pragma unroll
        for (int nt = 0; nt < 8; nt++) {
            int cg = s0 + nt * 8 + 2 * t;
            int d00 = rg0 - cg, d01 = d00 - 1;
            int d10 = rg1 - cg, d11 = d10 - 1;
            s[nt][0] = (d00 >= 0 && d00 < WIN) ? s[nt][0] * SCALE_F : -1e30f;
            s[nt][1] = (d01 >= 0 && d01 < WIN) ? s[nt][1] * SCALE_F : -1e30f;
            s[nt][2] = (d10 >= 0 && d10 < WIN) ? s[nt][2] * SCALE_F : -1e30f;
            s[nt][3] = (d11 >= 0 && d11 < WIN) ? s[nt][3] * SCALE_F : -1e30f;
            tm0 = fmaxf(tm0, fmaxf(s[nt][0], s[nt][1]));
            tm1 = fmaxf(tm1, fmaxf(s[nt][2], s[nt][3]));
        }
        tm0 = fmaxf(tm0, __shfl_xor_sync(0xffffffffu, tm0, 1));
        tm0 = fmaxf(tm0, __shfl_xor_sync(0xffffffffu, tm0, 2));
        tm1 = fmaxf(tm1, __shfl_xor_sync(0xffffffffu, tm1, 1));
        tm1 = fmaxf(tm1, __shfl_xor_sync(0xffffffffu, tm1, 2));

        float mn0 = fmaxf(mi0, tm0), mn1 = fmaxf(mi1, tm1);
        float al0 = __expf(mi0 - mn0), al1 = __expf(mi1 - mn1);
        mi0 = mn0; mi1 = mn1;
        float rs0 = 0.f, rs1 = 0.f;
        #pragma unroll
        for (int nt = 0; nt < 8; nt++) {
            float p00 = __expf(s[nt][0] - mn0);
            float p01 = __expf(s[nt][1] - mn0);
            float p10 = __expf(s[nt][2] - mn1);
            float p11 = __expf(s[nt][3] - mn1);
            rs0 += p00 + p01;
            rs1 += p10 + p11;
            int col = nt * 8 + 2 * t;
            *(uint2*)&Ps[(r0 + g    ) * QSTR + col] = make_uint2(f2tf(p00), f2tf(p01));
            *(uint2*)&Ps[(r0 + g + 8) * QSTR + col] = make_uint2(f2tf(p10), f2tf(p11));
            o[nt][0] *= al0; o[nt][1] *= al0;
            o[nt][2] *= al1; o[nt][3] *= al1;
        }
        rs0 += __shfl_xor_sync(0xffffffffu, rs0, 1);
        rs0 += __shfl_xor_sync(0xffffffffu, rs0, 2);
        rs1 += __shfl_xor_sync(0xffffffffu, rs1, 1);
        rs1 += __shfl_xor_sync(0xffffffffu, rs1, 2);
        li0 = li0 * al0 + rs0;
        li1 = li1 * al1 + rs1;
        __syncwarp();

        #pragma unroll
        for (int ks = 0; ks < 8; ks++) {
            const int kb = ks * 8;
            uint32_t a[4];
            a[0] = Ps[(r0 + g    ) * QSTR + kb + t];
            a[1] = Ps[(r0 + g + 8) * QSTR + kb + t];
            a[2] = Ps[(r0 + g    ) * QSTR + kb + t + 4];
            a[3] = Ps[(r0 + g + 8) * QSTR + kb + t + 4];
            #pragma unroll
            for (int nt = 0; nt < 8; nt++) {
                uint32_t b[2];
                b[0] = Vs[(kb + t    ) * VSTR + nt * 8 + g];
                b[1] = Vs[(kb + t + 4) * VSTR + nt * 8 + g];
                mma_tf32_16n8k8(o[nt], a, b);
            }
        }
    }

    // epilogue: normalize, emit tf32 for the O-projection GEMM
    float inv0 = 1.f / li0, inv1 = 1.f / li1;
    #pragma unroll
    for (int nt = 0; nt < 8; nt++) {
        int col = h * 64 + nt * 8 + 2 * t;
        *(uint2*)(g_att + (size_t)rg0 * CC + col) =
            make_uint2(f2tf(o[nt][0] * inv0), f2tf(o[nt][1] * inv0));
        *(uint2*)(g_att + (size_t)rg1 * CC + col) =
            make_uint2(f2tf(o[nt][2] * inv1), f2tf(o[nt][3] * inv1));
    }
}

// ---------------------------------------------------------------------------
extern "C" void kernel_launch(void* const* d_in, const int* in_sizes, int n_in,
                              void* d_out, int out_size)
{
    const float* x    = (const float*)d_in[0];
    const float* wqkv = (const float*)d_in[3];
    const float* wo   = (const float*)d_in[4];
    const float* qnw  = (const float*)d_in[5];
    const float* knw  = (const float*)d_in[6];
    const float* cosT = (const float*)d_in[7];
    const float* sinT = (const float*)d_in[8];
    float* out = (float*)d_out;

    float* p_qkv = nullptr;
    uint32_t *p_xt = nullptr, *p_wqkvt = nullptr, *p_wot = nullptr, *p_att = nullptr;
    cudaGetSymbolAddress((void**)&p_qkv, g_qkv);
    cudaGetSymbolAddress((void**)&p_xt, g_xt);
    cudaGetSymbolAddress((void**)&p_wqkvt, g_wqkvt);
    cudaGetSymbolAddress((void**)&p_wot, g_wot);
    cudaGetSymbolAddress((void**)&p_att, g_att);

    // 0) pre-convert fp32 -> tf32 (RN)
    cvt_tf32_k<<<(TT * CC / 4 + 255) / 256, 256>>>((const float4*)x, (uint4*)p_xt, TT * CC / 4);
    cvt_tf32_k<<<(3 * CC * CC / 4 + 255) / 256, 256>>>((const float4*)wqkv, (uint4*)p_wqkvt, 3 * CC * CC / 4);
    cvt_tf32_k<<<(CC * CC / 4 + 255) / 256, 256>>>((const float4*)wo, (uint4*)p_wot, CC * CC / 4);

    const int gsmem = 4 * CHUNK * 4;   // 73728 B
    cudaFuncSetAttribute(gemm_mma, cudaFuncAttributeMaxDynamicSharedMemorySize, gsmem);
    cudaFuncSetAttribute(attn_mma, cudaFuncAttributeMaxDynamicSharedMemorySize, ATT_SMEM);

    // 1) qkv = x @ w_qkv^T
    gemm_mma<<<dim3(3072 / 128, 4096 / 128), 256, gsmem>>>(p_xt, p_wqkvt, p_qkv, TT, 3 * CC, CC);

    // 2) rmsnorm + rope + v*0.5 -> tf32 [H][T][64]
    qkv_post<<<TT, 512>>>(cosT, sinT, qnw, knw);

    // 3) sliding-window attention -> tf32 att
    attn_mma<<<dim3(TT / 128, HH), 256, ATT_SMEM>>>();

    // 4) out = att @ w_o^T
    gemm_mma<<<dim3(1024 / 128, 4096 / 128), 256, gsmem>>>(p_att, p_wot, out, TT, CC, CC);
}